// round 1
// baseline (speedup 1.0000x reference)
#include <cuda_runtime.h>
#include <cstddef>

// ---------------- device scratch (no allocations allowed) ----------------
#define MAX_N 262144
__device__ float g_sbuf[MAX_N];  // s[n] = proj[n]·w_st
__device__ float g_v[128];       // proj_w @ w_st
__device__ float g_u[64];        // w_his2 @ w_st
__device__ float g_U[16];        // user_out[b] + b_u + b_st
__device__ float g_c;            // proj_b · w_st
__device__ float g_bh2;          // b_his2 · w_st

// ---------------- prep: tiny per-vector precomputation ----------------
__global__ void prep_kernel(const float* __restrict__ proj_w,
                            const float* __restrict__ proj_b,
                            const float* __restrict__ w_his2,
                            const float* __restrict__ b_his2,
                            const float* __restrict__ w_st,
                            const float* __restrict__ b_st,
                            const float* __restrict__ w_u,
                            const float* __restrict__ b_u,
                            const float* __restrict__ user_embedding,
                            const float* __restrict__ user_emb_table,
                            const float* __restrict__ theta,
                            const int* __restrict__ user_id,
                            int Bn)
{
    __shared__ float ws[128];
    int tid = threadIdx.x;
    if (tid < 128) ws[tid] = w_st[tid];
    __syncthreads();

    if (tid < 128) {
        float acc = 0.f;
        #pragma unroll 8
        for (int j = 0; j < 128; ++j) acc += proj_w[tid * 128 + j] * ws[j];
        g_v[tid] = acc;
    } else if (tid < 192) {
        int j = tid - 128;
        float acc = 0.f;
        #pragma unroll 8
        for (int d = 0; d < 128; ++d) acc += w_his2[j * 128 + d] * ws[d];
        g_u[j] = acc;
    } else if (tid < 192 + 16) {
        int b = tid - 192;
        if (b < Bn) {
            int uid = user_id[b];
            float th = theta[uid];
            float acc = 0.f;
            #pragma unroll 8
            for (int d = 0; d < 128; ++d) {
                float um = (1.f - th) * user_embedding[b * 128 + d]
                         + th * user_emb_table[(size_t)uid * 128 + d];
                acc += um * w_u[d];
            }
            g_U[b] = acc + b_u[0] + b_st[0];
        }
    } else if (tid == 208) {
        float acc = 0.f;
        for (int d = 0; d < 128; ++d) acc += proj_b[d] * ws[d];
        g_c = acc;
    } else if (tid == 209) {
        float acc = 0.f;
        for (int d = 0; d < 128; ++d) acc += b_his2[d] * ws[d];
        g_bh2 = acc;
    }
}

// ---------------- main sweep: s[n] = row·v + c ; out[b,n] = s[n] + U[b] ----------------
// 256 threads = 8 warps; block handles 128 nodes; warp handles 16 nodes,
// grouped 4-at-a-time for MLP. Coalesced float4 row loads; shuffle reduce;
// staged through smem then coalesced writes of all B output rows.
__global__ __launch_bounds__(256)
void main_kernel(const float* __restrict__ set_table,
                 float* __restrict__ out, int N, int Bn)
{
    __shared__ float sh_s[128];
    __shared__ float sh_U[16];
    int tid = threadIdx.x;
    int lane = tid & 31, warp = tid >> 5;
    if (tid < Bn) sh_U[tid] = g_U[tid];
    float4 v4 = reinterpret_cast<const float4*>(g_v)[lane];
    float cval = g_c;

    int base = blockIdx.x * 128;

    #pragma unroll
    for (int g = 0; g < 4; ++g) {
        int n0 = base + warp * 16 + g * 4;
        float4 r[4];
        #pragma unroll
        for (int i = 0; i < 4; ++i) {
            int n = n0 + i;
            if (n < N)
                r[i] = reinterpret_cast<const float4*>(set_table + (size_t)n * 128)[lane];
            else
                r[i] = make_float4(0.f, 0.f, 0.f, 0.f);
        }
        #pragma unroll
        for (int i = 0; i < 4; ++i) {
            float p = r[i].x * v4.x + r[i].y * v4.y + r[i].z * v4.z + r[i].w * v4.w;
            #pragma unroll
            for (int off = 16; off; off >>= 1)
                p += __shfl_xor_sync(0xffffffffu, p, off);
            int n = n0 + i;
            if (lane == 0 && n < N) {
                float s = p + cval;
                sh_s[warp * 16 + g * 4 + i] = s;
                g_sbuf[n] = s;
            }
        }
    }
    __syncthreads();

    int count = N - base; if (count > 128) count = 128;
    for (int idx = tid; idx < Bn * 128; idx += 256) {
        int b = idx >> 7, j = idx & 127;
        if (j < count)
            out[(size_t)b * N + base + j] = sh_s[j] + sh_U[b];
    }
}

// ---------------- beta overwrite (set semantics, idempotent store) ----------------
__global__ void beta_kernel(const int* __restrict__ now_nodes,
                            const int* __restrict__ his_nodes,
                            const float* __restrict__ alpha,
                            float* __restrict__ out, int N, int K, int BK)
{
    int t = blockIdx.x * blockDim.x + threadIdx.x;
    if (t >= 2 * BK) return;
    int which = t / BK, r = t - which * BK;
    int n = which ? his_nodes[r] : now_nodes[r];
    int b = r / K;
    out[(size_t)b * N + n] = (1.f - alpha[n]) * g_sbuf[n] + g_U[b];
}

// ---------------- corrections: now scatter-add + his MLP scatter-add ----------------
// one 64-thread block per entry; atomicAdd matches JAX duplicate-add semantics.
__global__ __launch_bounds__(64)
void corr_kernel(const int* __restrict__ now_nodes,
                 const int* __restrict__ his_nodes,
                 const float* __restrict__ alpha,
                 const float* __restrict__ station_embedding,
                 const float* __restrict__ raw_field_embed,
                 const float* __restrict__ w_st,
                 const float* __restrict__ w_his1,
                 const float* __restrict__ b_his1,
                 float* __restrict__ out, int N, int K, int BK)
{
    __shared__ float red[64];
    __shared__ float xsh[128];
    int t = threadIdx.x;
    int e = blockIdx.x;

    if (e < BK) {
        // now contribution: alpha[n] * (station_embedding[n] · w_st)
        int n = now_nodes[e], b = e / K;
        const float* row = station_embedding + (size_t)n * 128;
        float p = row[2 * t] * w_st[2 * t] + row[2 * t + 1] * w_st[2 * t + 1];
        red[t] = p;
        __syncthreads();
        for (int s = 32; s; s >>= 1) { if (t < s) red[t] += red[t + s]; __syncthreads(); }
        if (t == 0) atomicAdd(&out[(size_t)b * N + n], alpha[n] * red[0]);
    } else {
        // his contribution: alpha[n] * ( sum_j leaky(x·w1[:,j]+b1[j]) * u[j] + bh2 )
        e -= BK;
        int n = his_nodes[e], b = e / K;
        const float* row = raw_field_embed + (size_t)n * 128;
        xsh[t] = row[t];
        xsh[t + 64] = row[t + 64];
        __syncthreads();
        float acc = b_his1[t];
        #pragma unroll 8
        for (int d = 0; d < 128; ++d) acc += xsh[d] * w_his1[d * 64 + t];
        float ly = acc > 0.f ? acc : 0.01f * acc;
        red[t] = ly * g_u[t];
        __syncthreads();
        for (int s = 32; s; s >>= 1) { if (t < s) red[t] += red[t + s]; __syncthreads(); }
        if (t == 0) atomicAdd(&out[(size_t)b * N + n], alpha[n] * (red[0] + g_bh2));
    }
}

// ---------------- host launch ----------------
extern "C" void kernel_launch(void* const* d_in, const int* in_sizes, int n_in,
                              void* d_out, int out_size)
{
    // resolve input ordering at runtime:
    // dict order : ue, se, rfe, his, now, uid, uet, set, pw, pb, th, al, w1, b1, w2, b2, wst, bst, wu, bu
    // sig  order : ue, se, rfe, uet, set, pw, pb, th, al, w1, b1, w2, b2, wst, bst, wu, bu, his, now, uid
    int iUE, iSE, iRFE, iHIS, iNOW, iUID, iUET, iSET, iPW, iPB, iTH, iAL,
        iW1, iB1, iW2, iB2, iWST, iBST, iWU, iBU;
    if (in_sizes[3] < 100000) {
        iUE=0; iSE=1; iRFE=2; iHIS=3; iNOW=4; iUID=5; iUET=6; iSET=7; iPW=8; iPB=9;
        iTH=10; iAL=11; iW1=12; iB1=13; iW2=14; iB2=15; iWST=16; iBST=17; iWU=18; iBU=19;
    } else {
        iUE=0; iSE=1; iRFE=2; iUET=3; iSET=4; iPW=5; iPB=6; iTH=7; iAL=8; iW1=9;
        iB1=10; iW2=11; iB2=12; iWST=13; iBST=14; iWU=15; iBU=16; iHIS=17; iNOW=18; iUID=19;
    }

    const float* user_embedding    = (const float*)d_in[iUE];
    const float* station_embedding = (const float*)d_in[iSE];
    const float* raw_field_embed   = (const float*)d_in[iRFE];
    const float* user_emb_table    = (const float*)d_in[iUET];
    const float* station_emb_table = (const float*)d_in[iSET];
    const float* proj_w            = (const float*)d_in[iPW];
    const float* proj_b            = (const float*)d_in[iPB];
    const float* theta             = (const float*)d_in[iTH];
    const float* alpha             = (const float*)d_in[iAL];
    const float* w_his1            = (const float*)d_in[iW1];
    const float* b_his1            = (const float*)d_in[iB1];
    const float* w_his2            = (const float*)d_in[iW2];
    const float* b_his2            = (const float*)d_in[iB2];
    const float* w_st              = (const float*)d_in[iWST];
    const float* b_st              = (const float*)d_in[iBST];
    const float* w_u               = (const float*)d_in[iWU];
    const float* b_u               = (const float*)d_in[iBU];
    const int*   his_nodes         = (const int*)d_in[iHIS];
    const int*   now_nodes         = (const int*)d_in[iNOW];
    const int*   user_id           = (const int*)d_in[iUID];

    int B = in_sizes[iUE] / 128;       // 8
    int N = in_sizes[iAL];             // 60082
    int BK = in_sizes[iHIS];           // B*K = 256
    int K = BK / B;                    // 32

    float* out = (float*)d_out;
    (void)out_size; (void)n_in;

    prep_kernel<<<1, 256>>>(proj_w, proj_b, w_his2, b_his2, w_st, b_st,
                            w_u, b_u, user_embedding, user_emb_table,
                            theta, user_id, B);

    int grid = (N + 127) / 128;
    main_kernel<<<grid, 256>>>(station_emb_table, out, N, B);

    int bthreads = 2 * BK;
    beta_kernel<<<(bthreads + 255) / 256, 256>>>(now_nodes, his_nodes, alpha, out, N, K, BK);

    corr_kernel<<<2 * BK, 64>>>(now_nodes, his_nodes, alpha,
                                station_embedding, raw_field_embed,
                                w_st, w_his1, b_his1, out, N, K, BK);
}